// round 10
// baseline (speedup 1.0000x reference)
#include <cuda_runtime.h>

// Normalized correlation layer, GB300 sm_103a — round 10.
// Identity: sum((a-ma)(b-mb))/(sa*sb) = (S_ab - 25*ma*mb) * (1/sa)*(1/sb).
//
// Round-10 vs round-9: 512 threads (64c x 4jj x 2th, 3 j-phases) -> 128-reg
// budget, enabling an EXPLICIT pb double-buffer across the rho loop.
// Round-9's 768-thread config was capped at 85 regs: no room to prefetch
// next rho's 9 LDS.64 during the current FMA burst -> LDS latency and FMA
// issue anti-correlated (L1 55%, fma 30%, issue 35%, all < 60%).

#define NB 16
#define NR 37

typedef unsigned long long u64;

__device__ __forceinline__ u64 fma2_(u64 a, u64 b, u64 c) {
    u64 d; asm("fma.rn.f32x2 %0, %1, %2, %3;" : "=l"(d) : "l"(a), "l"(b), "l"(c)); return d;
}
__device__ __forceinline__ u64 mul2_(u64 a, u64 b) {
    u64 d; asm("mul.rn.f32x2 %0, %1, %2;" : "=l"(d) : "l"(a), "l"(b)); return d;
}
__device__ __forceinline__ u64 add2_(u64 a, u64 b) {
    u64 d; asm("add.rn.f32x2 %0, %1, %2;" : "=l"(d) : "l"(a), "l"(b)); return d;
}
__device__ __forceinline__ u64 pk2(float x, float y) {
    u64 r; asm("mov.b64 %0, {%1, %2};" : "=l"(r) : "f"(x), "f"(y)); return r;
}
__device__ __forceinline__ float2 upk2(u64 v) {
    float2 f; asm("mov.b64 {%0, %1}, %2;" : "=f"(f.x), "=f"(f.y) : "l"(v)); return f;
}

// Stats. g_nA = -25*mean1, g_rA = rstd1, layout [b][37][j][ch].
// Image2 stats w-pair packed, u64[b][39][t][ch].
__device__ float  g_nA [NB * NR * 12 * 128];
__device__ float  g_rA [NB * NR * 12 * 128];
__device__ float2 g_mBt[NB * 39 * 6 * 128];
__device__ float2 g_rBt[NB * 39 * 6 * 128];

// ---------------------------------------------------------------------------
// Pass 1: per-patch per-channel mean and rstd (unchanged).
// ---------------------------------------------------------------------------
__global__ __launch_bounds__(384) void nc_stats_kernel(
    const float* __restrict__ in1, const float* __restrict__ in2)
{
    __shared__ u64 slab[5 * 16 * 64];
    const int bx  = blockIdx.x;
    const int b   = blockIdx.y;
    const int tid = threadIdx.x;

    const bool img1 = bx < NR;
    const int  st   = img1 ? bx : bx - NR;
    const int  roff = img1 ? 2 : 4;
    const u64* inv  = (const u64*)(img1 ? in1 : in2);

    for (int i = tid; i < 5 * 16 * 64; i += 384) {
        int c = i & 63, col = (i >> 6) & 15, dr = i >> 10;
        int row = st + dr - roff;
        int cg  = col - 2;
        u64 v = 0ull;
        if ((unsigned)row < 37u && (unsigned)cg < 12u)
            v = inv[((b * 37 + row) * 12 + cg) * 64 + c];
        slab[i] = v;
    }
    __syncthreads();

    for (int t = tid; t < 12 * 64; t += 384) {
        int j = t >> 6, c = t & 63;
        u64 s = 0ull, q = 0ull;
        #pragma unroll
        for (int dr = 0; dr < 5; dr++) {
            #pragma unroll
            for (int dc = 0; dc < 5; dc++) {
                u64 v = slab[(dr * 16 + j + dc) * 64 + c];
                s = add2_(s, v);
                q = fma2_(v, v, q);
            }
        }
        float2 sf = upk2(s), qf = upk2(q);
        float mx = sf.x * 0.04f, my = sf.y * 0.04f;
        float vx = qf.x * 0.04f - mx * mx;
        float vy = qf.y * 0.04f - my * my;
        float rx = rsqrtf(vx), ry = rsqrtf(vy);

        if (img1) {
            int idx = ((b * 37 + st) * 12 + j) * 128 + 2 * c;
            g_nA[idx]     = -25.0f * mx;
            g_nA[idx + 1] = -25.0f * my;
            g_rA[idx]     = rx;
            g_rA[idx + 1] = ry;
        } else {
            float* mB = (float*)g_mBt;
            float* rB = (float*)g_rBt;
            int base = (((b * 39 + st) * 6 + (j >> 1)) * 128) * 2 + (j & 1);
            mB[base + 4 * c]     = mx;
            mB[base + 4 * c + 2] = my;
            rB[base + 4 * c]     = rx;
            rB[base + 4 * c + 2] = ry;
        }
    }
}

// ---------------------------------------------------------------------------
// Pass 2. Smem offsets (bytes).
// ---------------------------------------------------------------------------
#define PB_OFF     0                        // u64[9][15][64]         69120 B
#define A1F_OFF    69120                    // f32[5][16][80]         25600 B
#define SBM_OFF    94720                    // u64[5][6][64]          15360 B
#define SBR_OFF    110080                   // u64[5][6][64]          15360 B
#define STAGE_OFF  125440                   // f32[4][3848]           61568 B
#define STAGE_ROW  3848
#define SMEM_BYTES 187008

__global__ __launch_bounds__(512, 1) void nc_corr_kernel(
    const float* __restrict__ in1, const float* __restrict__ in2,
    float* __restrict__ out)
{
    extern __shared__ char smraw[];
    u64*   PB    = (u64*)smraw;
    float* A1F   = (float*)(smraw + A1F_OFF);
    u64*   SBM   = (u64*)(smraw + SBM_OFF);
    u64*   SBR   = (u64*)(smraw + SBR_OFF);
    float* stage = (float*)(smraw + STAGE_OFF);

    const int r   = blockIdx.x;
    const int b   = blockIdx.y;
    const int chv = blockIdx.z;

    const int tid  = threadIdx.x;
    // 16 warps: w = th*8 + jjp*4 + cq ; lane = jj01*16 + lc.
    const int w    = tid >> 5;
    const int lane = tid & 31;
    const int th   = w >> 3;           // 0..1
    const int jjp  = (w >> 2) & 1;     // 0..1
    const int cq   = w & 3;            // 0..3
    const int jj01 = lane >> 4;        // 0..1
    const int lc   = lane & 15;        // 0..15
    const int c    = cq * 16 + lc;     // 0..63
    const int jj   = jjp * 2 + jj01;   // 0..3
    const int ch   = chv * 64 + c;

    // ---- fills (linear tid) ----
    for (int i = tid; i < 9 * 15 * 64; i += 512) {
        int cc = i & 63, x = (i >> 6) % 15, row = i / (15 * 64);
        int irow = r + row - 4;
        float vlo = 0.f, vhi = 0.f;
        if ((unsigned)irow < 37u) {
            const float* base = in2 + ((b * 37 + irow) * 12) * 128 + chv * 64 + cc;
            int collo = x - 2, colhi = x - 1;
            if ((unsigned)collo < 12u) vlo = base[collo * 128];
            if ((unsigned)colhi < 12u) vhi = base[colhi * 128];
        }
        PB[i] = pk2(vlo, vhi);
    }
    for (int i = tid; i < 5 * 16 * 64; i += 512) {
        int cc = i & 63, col = (i >> 6) & 15, dr = i >> 10;
        int irow = r + dr - 2, icol = col - 2;
        float v = 0.f;
        if ((unsigned)irow < 37u && (unsigned)icol < 12u)
            v = in1[((b * 37 + irow) * 12 + icol) * 128 + chv * 64 + cc];
        A1F[(dr * 16 + col) * 80 + cc] = v;
    }
    // B-stats slabs: slot s holds row-start (r+s <= 38 ? r+s : r+s-2).
    for (int i = tid; i < 5 * 6 * 64; i += 512) {
        int cc = i & 63, t = (i >> 6) % 6, s = i / (6 * 64);
        int rs = r + s; if (rs > 38) rs -= 2;
        int gi = ((b * 39 + rs) * 6 + t) * 128 + chv * 64 + cc;
        SBM[i] = ((const u64*)g_mBt)[gi];
        SBR[i] = ((const u64*)g_rBt)[gi];
    }
    __syncthreads();

    #pragma unroll 1
    for (int ph = 0; ph < 3; ph++) {
        const int j = jj + 4 * ph;

        float a1f[5][5];
        u64 acc[5][3];
        #pragma unroll
        for (int d = 0; d < 5; d++)
            #pragma unroll
            for (int tt = 0; tt < 3; tt++) acc[d][tt] = 0ull;

        // Software-pipelined rho loop: pb double-buffered so rho+1's loads
        // issue before/under rho's FMA burst. All indices compile-time.
        u64 pb[2][9];
        #pragma unroll
        for (int k = 0; k < 9; k++)
            pb[0][k] = PB[(6 * th + k) * 64 + c];

        #pragma unroll
        for (int rho = 0; rho < 9; rho++) {
            const int cur = rho & 1;
            if (rho < 8) {
                #pragma unroll
                for (int k = 0; k < 9; k++)
                    pb[cur ^ 1][k] = PB[((rho + 1) * 15 + 6 * th + k) * 64 + c];
            }
            if (rho < 5) {
                #pragma unroll
                for (int dc = 0; dc < 5; dc++)
                    a1f[rho][dc] = A1F[(rho * 16 + j + dc) * 80 + c];
            }
            #pragma unroll
            for (int d = 0; d < 5; d++) {
                const int dr = rho - d;                 // compile-time
                if (dr >= 0 && dr < 5) {
                    #pragma unroll
                    for (int dc = 0; dc < 5; dc++) {
                        const u64 a = pk2(a1f[dr][dc], a1f[dr][dc]);
                        #pragma unroll
                        for (int tt = 0; tt < 3; tt++)
                            acc[d][tt] = fma2_(a, pb[cur][2 * tt + dc], acc[d][tt]);
                    }
                }
            }
        }

        // Epilogue. Stats from smem slot d (clamp folded into fill).
        // row2 duplication (r=35,36): d>=3 clamped -> result equals d-2.
        const int giA = ((b * 37 + r) * 12 + j) * 128 + ch;
        const float na = g_nA[giA];
        const float ra = g_rA[giA];
        const u64 na2 = pk2(na, na);
        const u64 ra2 = pk2(ra, ra);
        float* srow = stage + jj * STAGE_ROW + c * 60 + 6 * th;

        #pragma unroll
        for (int d = 0; d < 5; d++) {
            const bool clamp = (d >= 3) && (r + d > 38);
            const int sbase = (d * 6 + 3 * th) * 64 + c;
            #pragma unroll
            for (int tt = 0; tt < 3; tt++) {
                u64 s = acc[d][tt];
                if (d >= 3) s = clamp ? acc[d - 2][tt] : s;
                u64 mbp = SBM[sbase + tt * 64];
                u64 rbp = SBR[sbase + tt * 64];
                u64 res = mul2_(fma2_(na2, mbp, s), mul2_(ra2, rbp));
                *(u64*)(srow + 12 * d + 2 * tt) = res;
            }
        }
        __syncthreads();

        // Coalesced flush: 4 j-tiles x 960 float4 each (512 + 448 split).
        {
            float* obase = out + ((b * 37 + r) * 12 + 4 * ph) * 7680 + chv * 3840;
            #pragma unroll 1
            for (int jl = 0; jl < 4; jl++) {
                const float* st0 = stage + jl * STAGE_ROW;
                float* og = obase + jl * 7680;
                *(float4*)(og + tid * 4) = *(const float4*)(st0 + tid * 4);
                if (tid < 448)
                    *(float4*)(og + (512 + tid) * 4) =
                        *(const float4*)(st0 + (512 + tid) * 4);
            }
        }
        __syncthreads();
    }
}

// ---------------------------------------------------------------------------
extern "C" void kernel_launch(void* const* d_in, const int* in_sizes, int n_in,
                              void* d_out, int out_size)
{
    const float* in1 = (const float*)d_in[0];
    const float* in2 = (const float*)d_in[1];
    float* out = (float*)d_out;

    cudaFuncSetAttribute(nc_corr_kernel,
                         cudaFuncAttributeMaxDynamicSharedMemorySize, SMEM_BYTES);

    nc_stats_kernel<<<dim3(NR + 39, NB), 384>>>(in1, in2);
    nc_corr_kernel<<<dim3(NR, NB, 2), 512, SMEM_BYTES>>>(in1, in2, out);
}

// round 11
// speedup vs baseline: 1.0923x; 1.0923x over previous
#include <cuda_runtime.h>

// Normalized correlation layer, GB300 sm_103a — round 11.
// Identity: sum((a-ma)(b-mb))/(sa*sb) = (S_ab - 25*ma*mb) * (1/sa)*(1/sb).
//
// Round-11 vs round-9 (best 147us, 768 thr / 24 warps kept — warp count is
// the scarce resource; issue% scales with warps at ~constant stall/instr):
//  - PB per-thread-major u64[c][rho][16] (c-stride 145 -> conflict-free):
//    each rho's 9 pb values contiguous -> 4x LDS.128 + 1x LDS.64 (5 instr,
//    was 9) and base+imm addressing (kills pb IMADs; alu pipe was 18.8%).
//  - stats slabs removed from smem (r8-style coalesced LDG tail, measured
//    equal) to fit padded PB. smem 192KB.

#define NB 16
#define NR 37

typedef unsigned long long u64;

__device__ __forceinline__ u64 fma2_(u64 a, u64 b, u64 c) {
    u64 d; asm("fma.rn.f32x2 %0, %1, %2, %3;" : "=l"(d) : "l"(a), "l"(b), "l"(c)); return d;
}
__device__ __forceinline__ u64 mul2_(u64 a, u64 b) {
    u64 d; asm("mul.rn.f32x2 %0, %1, %2;" : "=l"(d) : "l"(a), "l"(b)); return d;
}
__device__ __forceinline__ u64 add2_(u64 a, u64 b) {
    u64 d; asm("add.rn.f32x2 %0, %1, %2;" : "=l"(d) : "l"(a), "l"(b)); return d;
}
__device__ __forceinline__ u64 pk2(float x, float y) {
    u64 r; asm("mov.b64 %0, {%1, %2};" : "=l"(r) : "f"(x), "f"(y)); return r;
}
__device__ __forceinline__ float2 upk2(u64 v) {
    float2 f; asm("mov.b64 {%0, %1}, %2;" : "=f"(f.x), "=f"(f.y) : "l"(v)); return f;
}

// Stats. g_nA = -25*mean1, g_rA = rstd1, layout [b][37][j][ch].
// Image2 stats w-pair packed, u64[b][39][t][ch].
__device__ float  g_nA [NB * NR * 12 * 128];
__device__ float  g_rA [NB * NR * 12 * 128];
__device__ float2 g_mBt[NB * 39 * 6 * 128];
__device__ float2 g_rBt[NB * 39 * 6 * 128];

// ---------------------------------------------------------------------------
// Pass 1: per-patch per-channel mean and rstd (unchanged).
// ---------------------------------------------------------------------------
__global__ __launch_bounds__(384) void nc_stats_kernel(
    const float* __restrict__ in1, const float* __restrict__ in2)
{
    __shared__ u64 slab[5 * 16 * 64];
    const int bx  = blockIdx.x;
    const int b   = blockIdx.y;
    const int tid = threadIdx.x;

    const bool img1 = bx < NR;
    const int  st   = img1 ? bx : bx - NR;
    const int  roff = img1 ? 2 : 4;
    const u64* inv  = (const u64*)(img1 ? in1 : in2);

    for (int i = tid; i < 5 * 16 * 64; i += 384) {
        int c = i & 63, col = (i >> 6) & 15, dr = i >> 10;
        int row = st + dr - roff;
        int cg  = col - 2;
        u64 v = 0ull;
        if ((unsigned)row < 37u && (unsigned)cg < 12u)
            v = inv[((b * 37 + row) * 12 + cg) * 64 + c];
        slab[i] = v;
    }
    __syncthreads();

    for (int t = tid; t < 12 * 64; t += 384) {
        int j = t >> 6, c = t & 63;
        u64 s = 0ull, q = 0ull;
        #pragma unroll
        for (int dr = 0; dr < 5; dr++) {
            #pragma unroll
            for (int dc = 0; dc < 5; dc++) {
                u64 v = slab[(dr * 16 + j + dc) * 64 + c];
                s = add2_(s, v);
                q = fma2_(v, v, q);
            }
        }
        float2 sf = upk2(s), qf = upk2(q);
        float mx = sf.x * 0.04f, my = sf.y * 0.04f;
        float vx = qf.x * 0.04f - mx * mx;
        float vy = qf.y * 0.04f - my * my;
        float rx = rsqrtf(vx), ry = rsqrtf(vy);

        if (img1) {
            int idx = ((b * 37 + st) * 12 + j) * 128 + 2 * c;
            g_nA[idx]     = -25.0f * mx;
            g_nA[idx + 1] = -25.0f * my;
            g_rA[idx]     = rx;
            g_rA[idx + 1] = ry;
        } else {
            float* mB = (float*)g_mBt;
            float* rB = (float*)g_rBt;
            int base = (((b * 39 + st) * 6 + (j >> 1)) * 128) * 2 + (j & 1);
            mB[base + 4 * c]     = mx;
            mB[base + 4 * c + 2] = my;
            rB[base + 4 * c]     = rx;
            rB[base + 4 * c + 2] = ry;
        }
    }
}

// ---------------------------------------------------------------------------
// Pass 2. Smem (bytes):
//   PB    u64[64][145]   (per-c row: [rho][16], x<15 valid; pad 145)  74240
//   A1F   f32[5][16][80]                                              25600
//   stage f32[6][3848]                                                92352
// ---------------------------------------------------------------------------
#define PB_CSTRIDE 145
#define A1F_OFF    74240
#define STAGE_OFF  99840
#define STAGE_ROW  3848
#define SMEM_BYTES 192192

__global__ __launch_bounds__(768, 1) void nc_corr_kernel(
    const float* __restrict__ in1, const float* __restrict__ in2,
    float* __restrict__ out)
{
    extern __shared__ char smraw[];
    u64*   PB    = (u64*)smraw;
    float* A1F   = (float*)(smraw + A1F_OFF);
    float* stage = (float*)(smraw + STAGE_OFF);

    const int r   = blockIdx.x;
    const int b   = blockIdx.y;
    const int chv = blockIdx.z;

    const int tid  = threadIdx.x;
    // 24 warps: w = th*12 + jjp*4 + cq ; lane = jj01*16 + lc.
    const int w    = tid >> 5;
    const int lane = tid & 31;
    const int th   = w / 12;           // 0..1
    const int jjp  = (w % 12) >> 2;    // 0..2
    const int cq   = w & 3;            // 0..3
    const int jj01 = lane >> 4;        // 0..1
    const int lc   = lane & 15;        // 0..15
    const int c    = cq * 16 + lc;     // 0..63
    const int jj   = jjp * 2 + jj01;   // 0..5
    const int ch   = chv * 64 + c;

    // ---- fills (linear tid) ----
    // PB[cc][rho][x] = (A2pad[x], A2pad[x+1]) for pad2 row r+rho, x<15.
    for (int i = tid; i < 9 * 15 * 64; i += 768) {
        int cc = i & 63, x = (i >> 6) % 15, row = i / (15 * 64);
        int irow = r + row - 4;
        float vlo = 0.f, vhi = 0.f;
        if ((unsigned)irow < 37u) {
            const float* base = in2 + ((b * 37 + irow) * 12) * 128 + chv * 64 + cc;
            int collo = x - 2, colhi = x - 1;
            if ((unsigned)collo < 12u) vlo = base[collo * 128];
            if ((unsigned)colhi < 12u) vhi = base[colhi * 128];
        }
        PB[cc * PB_CSTRIDE + row * 16 + x] = pk2(vlo, vhi);
    }
    // A1F[dr][col][c-pad80] = scalar f32 image1 value, pad1 row r+dr.
    for (int i = tid; i < 5 * 16 * 64; i += 768) {
        int cc = i & 63, col = (i >> 6) & 15, dr = i >> 10;
        int irow = r + dr - 2, icol = col - 2;
        float v = 0.f;
        if ((unsigned)irow < 37u && (unsigned)icol < 12u)
            v = in1[((b * 37 + irow) * 12 + icol) * 128 + chv * 64 + cc];
        A1F[(dr * 16 + col) * 80 + cc] = v;
    }
    __syncthreads();

    const u64* mBv = (const u64*)g_mBt;
    const u64* rBv = (const u64*)g_rBt;
    const u64* PBc = PB + c * PB_CSTRIDE + 6 * th;   // this thread's pb base

    #pragma unroll 1
    for (int ph = 0; ph < 2; ph++) {
        const int j = jj + 6 * ph;

        float a1f[5][5];
        u64 acc[5][3];
        #pragma unroll
        for (int d = 0; d < 5; d++)
            #pragma unroll
            for (int tt = 0; tt < 3; tt++) acc[d][tt] = 0ull;

        // Static rho loop; pb row is contiguous: 4x LDS.128 + 1x LDS.64.
        #pragma unroll
        for (int rho = 0; rho < 9; rho++) {
            if (rho < 5) {
                #pragma unroll
                for (int dc = 0; dc < 5; dc++)
                    a1f[rho][dc] = A1F[(rho * 16 + j + dc) * 80 + c];
            }
            u64 pb[9];
            {
                const u64* p = PBc + rho * 16;       // 16B-aligned (6*th even)
                uint4 q0 = *(const uint4*)(p + 0);
                uint4 q1 = *(const uint4*)(p + 2);
                uint4 q2 = *(const uint4*)(p + 4);
                uint4 q3 = *(const uint4*)(p + 6);
                pb[0] = ((u64)q0.y << 32) | q0.x;  pb[1] = ((u64)q0.w << 32) | q0.z;
                pb[2] = ((u64)q1.y << 32) | q1.x;  pb[3] = ((u64)q1.w << 32) | q1.z;
                pb[4] = ((u64)q2.y << 32) | q2.x;  pb[5] = ((u64)q2.w << 32) | q2.z;
                pb[6] = ((u64)q3.y << 32) | q3.x;  pb[7] = ((u64)q3.w << 32) | q3.z;
                pb[8] = p[8];
            }

            #pragma unroll
            for (int d = 0; d < 5; d++) {
                const int dr = rho - d;                 // compile-time
                if (dr >= 0 && dr < 5) {
                    #pragma unroll
                    for (int dc = 0; dc < 5; dc++) {
                        const u64 a = pk2(a1f[dr][dc], a1f[dr][dc]);
                        #pragma unroll
                        for (int tt = 0; tt < 3; tt++)
                            acc[d][tt] = fma2_(a, pb[2 * tt + dc], acc[d][tt]);
                    }
                }
            }
        }

        // Epilogue. Stats via coalesced LDG (lane-contiguous in ch).
        // row2 duplication (r=35,36): d>=3 clamped -> result equals d-2.
        const int giA = ((b * 37 + r) * 12 + j) * 128 + ch;
        const float na = g_nA[giA];
        const float ra = g_rA[giA];
        const u64 na2 = pk2(na, na);
        const u64 ra2 = pk2(ra, ra);
        float* srow = stage + jj * STAGE_ROW + c * 60 + 6 * th;

        #pragma unroll
        for (int d = 0; d < 5; d++) {
            bool clamp = false;
            int  rowB  = r + d;
            if (d >= 3) { clamp = (r + d > 38); if (clamp) rowB = r + d - 2; }
            const int gbase = ((b * 39 + rowB) * 6 + 3 * th) * 128 + ch;
            #pragma unroll
            for (int tt = 0; tt < 3; tt++) {
                u64 s = acc[d][tt];
                if (d >= 3) s = clamp ? acc[d - 2][tt] : s;
                u64 mbp = mBv[gbase + tt * 128];
                u64 rbp = rBv[gbase + tt * 128];
                u64 res = mul2_(fma2_(na2, mbp, s), mul2_(ra2, rbp));
                *(u64*)(srow + 12 * d + 2 * tt) = res;
            }
        }
        __syncthreads();

        // Coalesced flush: 6 j-tiles x 960 float4 (768 + 192 split).
        {
            float* obase = out + ((b * 37 + r) * 12 + 6 * ph) * 7680 + chv * 3840;
            #pragma unroll 1
            for (int jl = 0; jl < 6; jl++) {
                const float* st0 = stage + jl * STAGE_ROW;
                float* og = obase + jl * 7680;
                *(float4*)(og + tid * 4) = *(const float4*)(st0 + tid * 4);
                if (tid < 192)
                    *(float4*)(og + (768 + tid) * 4) =
                        *(const float4*)(st0 + (768 + tid) * 4);
            }
        }
        __syncthreads();
    }
}

// ---------------------------------------------------------------------------
extern "C" void kernel_launch(void* const* d_in, const int* in_sizes, int n_in,
                              void* d_out, int out_size)
{
    const float* in1 = (const float*)d_in[0];
    const float* in2 = (const float*)d_in[1];
    float* out = (float*)d_out;

    cudaFuncSetAttribute(nc_corr_kernel,
                         cudaFuncAttributeMaxDynamicSharedMemorySize, SMEM_BYTES);

    nc_stats_kernel<<<dim3(NR + 39, NB), 384>>>(in1, in2);
    nc_corr_kernel<<<dim3(NR, NB, 2), 768, SMEM_BYTES>>>(in1, in2, out);
}

// round 12
// speedup vs baseline: 1.1797x; 1.0800x over previous
#include <cuda_runtime.h>

// Normalized correlation layer, GB300 sm_103a — round 12.
// Identity: sum((a-ma)(b-mb))/(sa*sb) = (S_ab - 25*ma*mb) * (1/sa)*(1/sb).
//
// Round-12 vs round-9/11 (147us plateau, inner loop kept IDENTICAL):
//  - CTA split by c-QUARTER (32 channels): smem 192KB -> 93.6KB => TWO
//    independent CTAs per SM at the same total warp count (2x12) and the
//    same 85-reg budget. One CTA's fill (gmem-latency) / flush (store)
//    sections now overlap the other CTA's FMA bursts; barriers desync.
//    Rounds 8-11 showed all metrics frozen at 1 CTA/SM regardless of
//    instruction mix -> phase serialization is the remaining suspect.
//  - c == lane (32 channels): all smem traffic conflict-free by construction.

#define NB 16
#define NR 37

typedef unsigned long long u64;

__device__ __forceinline__ u64 fma2_(u64 a, u64 b, u64 c) {
    u64 d; asm("fma.rn.f32x2 %0, %1, %2, %3;" : "=l"(d) : "l"(a), "l"(b), "l"(c)); return d;
}
__device__ __forceinline__ u64 mul2_(u64 a, u64 b) {
    u64 d; asm("mul.rn.f32x2 %0, %1, %2;" : "=l"(d) : "l"(a), "l"(b)); return d;
}
__device__ __forceinline__ u64 add2_(u64 a, u64 b) {
    u64 d; asm("add.rn.f32x2 %0, %1, %2;" : "=l"(d) : "l"(a), "l"(b)); return d;
}
__device__ __forceinline__ u64 pk2(float x, float y) {
    u64 r; asm("mov.b64 %0, {%1, %2};" : "=l"(r) : "f"(x), "f"(y)); return r;
}
__device__ __forceinline__ float2 upk2(u64 v) {
    float2 f; asm("mov.b64 {%0, %1}, %2;" : "=f"(f.x), "=f"(f.y) : "l"(v)); return f;
}

// Stats. g_nA = -25*mean1, g_rA = rstd1, layout [b][37][j][ch].
// Image2 stats w-pair packed, u64[b][39][t][ch].
__device__ float  g_nA [NB * NR * 12 * 128];
__device__ float  g_rA [NB * NR * 12 * 128];
__device__ float2 g_mBt[NB * 39 * 6 * 128];
__device__ float2 g_rBt[NB * 39 * 6 * 128];

// ---------------------------------------------------------------------------
// Pass 1: per-patch per-channel mean and rstd (unchanged).
// ---------------------------------------------------------------------------
__global__ __launch_bounds__(384) void nc_stats_kernel(
    const float* __restrict__ in1, const float* __restrict__ in2)
{
    __shared__ u64 slab[5 * 16 * 64];
    const int bx  = blockIdx.x;
    const int b   = blockIdx.y;
    const int tid = threadIdx.x;

    const bool img1 = bx < NR;
    const int  st   = img1 ? bx : bx - NR;
    const int  roff = img1 ? 2 : 4;
    const u64* inv  = (const u64*)(img1 ? in1 : in2);

    for (int i = tid; i < 5 * 16 * 64; i += 384) {
        int c = i & 63, col = (i >> 6) & 15, dr = i >> 10;
        int row = st + dr - roff;
        int cg  = col - 2;
        u64 v = 0ull;
        if ((unsigned)row < 37u && (unsigned)cg < 12u)
            v = inv[((b * 37 + row) * 12 + cg) * 64 + c];
        slab[i] = v;
    }
    __syncthreads();

    for (int t = tid; t < 12 * 64; t += 384) {
        int j = t >> 6, c = t & 63;
        u64 s = 0ull, q = 0ull;
        #pragma unroll
        for (int dr = 0; dr < 5; dr++) {
            #pragma unroll
            for (int dc = 0; dc < 5; dc++) {
                u64 v = slab[(dr * 16 + j + dc) * 64 + c];
                s = add2_(s, v);
                q = fma2_(v, v, q);
            }
        }
        float2 sf = upk2(s), qf = upk2(q);
        float mx = sf.x * 0.04f, my = sf.y * 0.04f;
        float vx = qf.x * 0.04f - mx * mx;
        float vy = qf.y * 0.04f - my * my;
        float rx = rsqrtf(vx), ry = rsqrtf(vy);

        if (img1) {
            int idx = ((b * 37 + st) * 12 + j) * 128 + 2 * c;
            g_nA[idx]     = -25.0f * mx;
            g_nA[idx + 1] = -25.0f * my;
            g_rA[idx]     = rx;
            g_rA[idx + 1] = ry;
        } else {
            float* mB = (float*)g_mBt;
            float* rB = (float*)g_rBt;
            int base = (((b * 39 + st) * 6 + (j >> 1)) * 128) * 2 + (j & 1);
            mB[base + 4 * c]     = mx;
            mB[base + 4 * c + 2] = my;
            rB[base + 4 * c]     = rx;
            rB[base + 4 * c + 2] = ry;
        }
    }
}

// ---------------------------------------------------------------------------
// Pass 2. CTA per (r, b, c-quarter). 384 thr = 32 c (lane) x 6 jj x 2 th.
// Smem (bytes): PB u64[9][15][32] = 34560; A1F f32[5][16][40] = 12800;
//               stage f32[6][1928] = 46272.  Total 93632 -> 2 CTAs/SM.
// ---------------------------------------------------------------------------
#define A1F_OFF    34560
#define STAGE_OFF  47360
#define STAGE_ROW  1928
#define SMEM_BYTES 93632

__global__ __launch_bounds__(384, 2) void nc_corr_kernel(
    const float* __restrict__ in1, const float* __restrict__ in2,
    float* __restrict__ out)
{
    extern __shared__ char smraw[];
    u64*   PB    = (u64*)smraw;
    float* A1F   = (float*)(smraw + A1F_OFF);
    float* stage = (float*)(smraw + STAGE_OFF);

    const int r   = blockIdx.x;
    const int b   = blockIdx.y;
    const int chq = blockIdx.z;        // c-quarter: 0..3

    const int tid = threadIdx.x;
    const int c   = tid & 31;          // channel within quarter == lane
    const int w   = tid >> 5;          // 0..11
    const int jj  = w % 6;             // 0..5
    const int th  = w / 6;             // 0..1
    const int ch  = chq * 32 + c;      // global channel

    // ---- fills (linear tid) ----
    // PB[row][x][c] = (A2pad[x], A2pad[x+1]) for pad2 row r+row, x<15.
    for (int i = tid; i < 9 * 15 * 32; i += 384) {
        int cc = i & 31, x = (i >> 5) % 15, row = i / (15 * 32);
        int irow = r + row - 4;
        float vlo = 0.f, vhi = 0.f;
        if ((unsigned)irow < 37u) {
            const float* base = in2 + ((b * 37 + irow) * 12) * 128 + chq * 32 + cc;
            int collo = x - 2, colhi = x - 1;
            if ((unsigned)collo < 12u) vlo = base[collo * 128];
            if ((unsigned)colhi < 12u) vhi = base[colhi * 128];
        }
        PB[i] = pk2(vlo, vhi);
    }
    // A1F[dr][col][c-pad40] = scalar f32 image1 value, pad1 row r+dr.
    for (int i = tid; i < 5 * 16 * 32; i += 384) {
        int cc = i & 31, col = (i >> 5) & 15, dr = i >> 9;
        int irow = r + dr - 2, icol = col - 2;
        float v = 0.f;
        if ((unsigned)irow < 37u && (unsigned)icol < 12u)
            v = in1[((b * 37 + irow) * 12 + icol) * 128 + chq * 32 + cc];
        A1F[(dr * 16 + col) * 40 + cc] = v;
    }
    __syncthreads();

    const u64* mBv = (const u64*)g_mBt;
    const u64* rBv = (const u64*)g_rBt;

    #pragma unroll 1
    for (int ph = 0; ph < 2; ph++) {
        const int j = jj + 6 * ph;

        float a1f[5][5];
        u64 acc[5][3];
        #pragma unroll
        for (int d = 0; d < 5; d++)
            #pragma unroll
            for (int tt = 0; tt < 3; tt++) acc[d][tt] = 0ull;

        // Static rho loop (identical dataflow to the 147us kernels).
        #pragma unroll
        for (int rho = 0; rho < 9; rho++) {
            if (rho < 5) {
                #pragma unroll
                for (int dc = 0; dc < 5; dc++)
                    a1f[rho][dc] = A1F[(rho * 16 + j + dc) * 40 + c];
            }
            u64 pb[9];
            #pragma unroll
            for (int k = 0; k < 9; k++)
                pb[k] = PB[(rho * 15 + 6 * th + k) * 32 + c];

            #pragma unroll
            for (int d = 0; d < 5; d++) {
                const int dr = rho - d;                 // compile-time
                if (dr >= 0 && dr < 5) {
                    #pragma unroll
                    for (int dc = 0; dc < 5; dc++) {
                        const u64 a = pk2(a1f[dr][dc], a1f[dr][dc]);
                        #pragma unroll
                        for (int tt = 0; tt < 3; tt++)
                            acc[d][tt] = fma2_(a, pb[2 * tt + dc], acc[d][tt]);
                    }
                }
            }
        }

        // Epilogue. Stats via coalesced LDG (lane-contiguous in ch).
        // row2 duplication (r=35,36): d>=3 clamped -> result equals d-2.
        const int giA = ((b * 37 + r) * 12 + j) * 128 + ch;
        const float na = g_nA[giA];
        const float ra = g_rA[giA];
        const u64 na2 = pk2(na, na);
        const u64 ra2 = pk2(ra, ra);
        float* srow = stage + jj * STAGE_ROW + c * 60 + 6 * th;

        #pragma unroll
        for (int d = 0; d < 5; d++) {
            bool clamp = false;
            int  rowB  = r + d;
            if (d >= 3) { clamp = (r + d > 38); if (clamp) rowB = r + d - 2; }
            const int gbase = ((b * 39 + rowB) * 6 + 3 * th) * 128 + ch;
            #pragma unroll
            for (int tt = 0; tt < 3; tt++) {
                u64 s = acc[d][tt];
                if (d >= 3) s = clamp ? acc[d - 2][tt] : s;
                u64 mbp = mBv[gbase + tt * 128];
                u64 rbp = rBv[gbase + tt * 128];
                u64 res = mul2_(fma2_(na2, mbp, s), mul2_(ra2, rbp));
                *(u64*)(srow + 12 * d + 2 * tt) = res;
            }
        }
        __syncthreads();

        // Coalesced flush: 6 j-tiles, each 32c*60w = 1920 contiguous floats
        // (480 float4 = 384 + 96 split).
        {
            float* obase = out + ((b * 37 + r) * 12 + 6 * ph) * 7680 + chq * 1920;
            #pragma unroll 1
            for (int jl = 0; jl < 6; jl++) {
                const float* st0 = stage + jl * STAGE_ROW;
                float* og = obase + jl * 7680;
                *(float4*)(og + tid * 4) = *(const float4*)(st0 + tid * 4);
                if (tid < 96)
                    *(float4*)(og + (384 + tid) * 4) =
                        *(const float4*)(st0 + (384 + tid) * 4);
            }
        }
        __syncthreads();
    }
}

// ---------------------------------------------------------------------------
extern "C" void kernel_launch(void* const* d_in, const int* in_sizes, int n_in,
                              void* d_out, int out_size)
{
    const float* in1 = (const float*)d_in[0];
    const float* in2 = (const float*)d_in[1];
    float* out = (float*)d_out;

    cudaFuncSetAttribute(nc_corr_kernel,
                         cudaFuncAttributeMaxDynamicSharedMemorySize, SMEM_BYTES);

    nc_stats_kernel<<<dim3(NR + 39, NB), 384>>>(in1, in2);
    nc_corr_kernel<<<dim3(NR, NB, 4), 384, SMEM_BYTES>>>(in1, in2, out);
}

// round 13
// speedup vs baseline: 1.2417x; 1.0526x over previous
#include <cuda_runtime.h>

// Normalized correlation layer, GB300 sm_103a — round 13.
// Identity: sum((a-ma)(b-mb))/(sa*sb) = (S_ab - 25*ma*mb) * (1/sa)*(1/sb).
//
// Round-13 vs round-12 (inner FMA structure identical; crossbar-targeted):
// Accounting showed smem crossbar demand ~152K cyc matches measured L1
// busy (58% x 250K) -> crossbar bytes are the cost driver.
//  - PB pair slab (every A2 value stored twice) -> RAW natural-pair slab
//    u64[9][8][32]: even-x pairs = direct LDS.64 (5/rho), odd-x pairs
//    BUILT from two loaded neighbors (4 register-selects). pb crossbar
//    324 -> 180 cyc/warp; smem -16KB.
//  - stage c-stride 60 -> 62 floats: STS bank conflict 4-way -> 2-way
//    (240 -> 120 cyc/warp). Flush uses u64 ops, division-free indices.

#define NB 16
#define NR 37

typedef unsigned long long u64;

__device__ __forceinline__ u64 fma2_(u64 a, u64 b, u64 c) {
    u64 d; asm("fma.rn.f32x2 %0, %1, %2, %3;" : "=l"(d) : "l"(a), "l"(b), "l"(c)); return d;
}
__device__ __forceinline__ u64 mul2_(u64 a, u64 b) {
    u64 d; asm("mul.rn.f32x2 %0, %1, %2;" : "=l"(d) : "l"(a), "l"(b)); return d;
}
__device__ __forceinline__ u64 add2_(u64 a, u64 b) {
    u64 d; asm("add.rn.f32x2 %0, %1, %2;" : "=l"(d) : "l"(a), "l"(b)); return d;
}
__device__ __forceinline__ u64 pk2(float x, float y) {
    u64 r; asm("mov.b64 %0, {%1, %2};" : "=l"(r) : "f"(x), "f"(y)); return r;
}
__device__ __forceinline__ float2 upk2(u64 v) {
    float2 f; asm("mov.b64 {%0, %1}, %2;" : "=f"(f.x), "=f"(f.y) : "l"(v)); return f;
}

// Stats. g_nA = -25*mean1, g_rA = rstd1, layout [b][37][j][ch].
// Image2 stats w-pair packed, u64[b][39][t][ch].
__device__ float  g_nA [NB * NR * 12 * 128];
__device__ float  g_rA [NB * NR * 12 * 128];
__device__ float2 g_mBt[NB * 39 * 6 * 128];
__device__ float2 g_rBt[NB * 39 * 6 * 128];

// ---------------------------------------------------------------------------
// Pass 1: per-patch per-channel mean and rstd (unchanged).
// ---------------------------------------------------------------------------
__global__ __launch_bounds__(384) void nc_stats_kernel(
    const float* __restrict__ in1, const float* __restrict__ in2)
{
    __shared__ u64 slab[5 * 16 * 64];
    const int bx  = blockIdx.x;
    const int b   = blockIdx.y;
    const int tid = threadIdx.x;

    const bool img1 = bx < NR;
    const int  st   = img1 ? bx : bx - NR;
    const int  roff = img1 ? 2 : 4;
    const u64* inv  = (const u64*)(img1 ? in1 : in2);

    for (int i = tid; i < 5 * 16 * 64; i += 384) {
        int c = i & 63, col = (i >> 6) & 15, dr = i >> 10;
        int row = st + dr - roff;
        int cg  = col - 2;
        u64 v = 0ull;
        if ((unsigned)row < 37u && (unsigned)cg < 12u)
            v = inv[((b * 37 + row) * 12 + cg) * 64 + c];
        slab[i] = v;
    }
    __syncthreads();

    for (int t = tid; t < 12 * 64; t += 384) {
        int j = t >> 6, c = t & 63;
        u64 s = 0ull, q = 0ull;
        #pragma unroll
        for (int dr = 0; dr < 5; dr++) {
            #pragma unroll
            for (int dc = 0; dc < 5; dc++) {
                u64 v = slab[(dr * 16 + j + dc) * 64 + c];
                s = add2_(s, v);
                q = fma2_(v, v, q);
            }
        }
        float2 sf = upk2(s), qf = upk2(q);
        float mx = sf.x * 0.04f, my = sf.y * 0.04f;
        float vx = qf.x * 0.04f - mx * mx;
        float vy = qf.y * 0.04f - my * my;
        float rx = rsqrtf(vx), ry = rsqrtf(vy);

        if (img1) {
            int idx = ((b * 37 + st) * 12 + j) * 128 + 2 * c;
            g_nA[idx]     = -25.0f * mx;
            g_nA[idx + 1] = -25.0f * my;
            g_rA[idx]     = rx;
            g_rA[idx + 1] = ry;
        } else {
            float* mB = (float*)g_mBt;
            float* rB = (float*)g_rBt;
            int base = (((b * 39 + st) * 6 + (j >> 1)) * 128) * 2 + (j & 1);
            mB[base + 4 * c]     = mx;
            mB[base + 4 * c + 2] = my;
            rB[base + 4 * c]     = rx;
            rB[base + 4 * c + 2] = ry;
        }
    }
}

// ---------------------------------------------------------------------------
// Pass 2. CTA per (r, b, c-quarter). 384 thr = 32 c (lane) x 6 jj x 2 th.
// Smem: PBraw u64[9][8][32] = 18432 B; A1F f32[5][16][40] = 12800 B;
//       stage f32[6][1984] = 47616 B.  Total 78848 B -> 2 CTAs/SM.
// ---------------------------------------------------------------------------
#define A1F_OFF    18432
#define STAGE_OFF  31232
#define STAGE_ROW  1984          /* floats per j-tile (62 per c) */
#define SMEM_BYTES 78848

__global__ __launch_bounds__(384, 2) void nc_corr_kernel(
    const float* __restrict__ in1, const float* __restrict__ in2,
    float* __restrict__ out)
{
    extern __shared__ char smraw[];
    u64*   PBraw = (u64*)smraw;                    // [rho][i][c], i = u64 col-pair
    float* A1F   = (float*)(smraw + A1F_OFF);
    float* stage = (float*)(smraw + STAGE_OFF);

    const int r   = blockIdx.x;
    const int b   = blockIdx.y;
    const int chq = blockIdx.z;        // c-quarter: 0..3

    const int tid = threadIdx.x;
    const int c   = tid & 31;          // channel within quarter == lane
    const int w   = tid >> 5;          // 0..11
    const int jj  = w % 6;             // 0..5
    const int th  = w / 6;             // 0..1
    const int ch  = chq * 32 + c;      // global channel

    // ---- fills (linear tid) ----
    // PBraw[row][i][c] = (A2pad[2i], A2pad[2i+1]) for pad2 row r+row.
    for (int i = tid; i < 9 * 8 * 32; i += 384) {
        int cc = i & 31, ii = (i >> 5) & 7, row = i >> 8;
        int irow = r + row - 4;
        float vlo = 0.f, vhi = 0.f;
        if ((unsigned)irow < 37u) {
            const float* base = in2 + ((b * 37 + irow) * 12) * 128 + chq * 32 + cc;
            int collo = 2 * ii - 2, colhi = 2 * ii - 1;
            if ((unsigned)collo < 12u) vlo = base[collo * 128];
            if ((unsigned)colhi < 12u) vhi = base[colhi * 128];
        }
        PBraw[i] = pk2(vlo, vhi);
    }
    // A1F[dr][col][c-pad40] = scalar f32 image1 value, pad1 row r+dr.
    for (int i = tid; i < 5 * 16 * 32; i += 384) {
        int cc = i & 31, col = (i >> 5) & 15, dr = i >> 9;
        int irow = r + dr - 2, icol = col - 2;
        float v = 0.f;
        if ((unsigned)irow < 37u && (unsigned)icol < 12u)
            v = in1[((b * 37 + irow) * 12 + icol) * 128 + chq * 32 + cc];
        A1F[(dr * 16 + col) * 40 + cc] = v;
    }
    __syncthreads();

    // Division-free flush indices (u64 elements; 960 per tile, 384 threads).
    const int g2 = tid + 384;
    const int c1 = tid / 30,  k1 = tid - 30 * c1;
    const int c2 = g2 / 30,   k2 = g2 - 30 * c2;
    const int g3 = tid + 768;
    const int c3 = g3 / 30,   k3 = g3 - 30 * c3;   // used only if tid < 192

    const u64* mBv = (const u64*)g_mBt;
    const u64* rBv = (const u64*)g_rBt;

    #pragma unroll 1
    for (int ph = 0; ph < 2; ph++) {
        const int j = jj + 6 * ph;

        float a1f[5][5];
        u64 acc[5][3];
        #pragma unroll
        for (int d = 0; d < 5; d++)
            #pragma unroll
            for (int tt = 0; tt < 3; tt++) acc[d][tt] = 0ull;

        // Static rho loop. pb[k] covers padded cols x = 6*th + k .. +1.
        // Even k: direct natural-pair load. Odd k: built from neighbors.
        #pragma unroll
        for (int rho = 0; rho < 9; rho++) {
            if (rho < 5) {
                #pragma unroll
                for (int dc = 0; dc < 5; dc++)
                    a1f[rho][dc] = A1F[(rho * 16 + j + dc) * 40 + c];
            }
            u64 e[5];
            #pragma unroll
            for (int q = 0; q < 5; q++)
                e[q] = PBraw[(rho * 8 + 3 * th + q) * 32 + c];

            u64 pb[9];
            #pragma unroll
            for (int m = 0; m < 5; m++) pb[2 * m] = e[m];
            #pragma unroll
            for (int m = 0; m < 4; m++) {
                float2 lo = upk2(e[m]);
                float2 hi = upk2(e[m + 1]);
                pb[2 * m + 1] = pk2(lo.y, hi.x);
            }

            #pragma unroll
            for (int d = 0; d < 5; d++) {
                const int dr = rho - d;                 // compile-time
                if (dr >= 0 && dr < 5) {
                    #pragma unroll
                    for (int dc = 0; dc < 5; dc++) {
                        const u64 a = pk2(a1f[dr][dc], a1f[dr][dc]);
                        #pragma unroll
                        for (int tt = 0; tt < 3; tt++)
                            acc[d][tt] = fma2_(a, pb[2 * tt + dc], acc[d][tt]);
                    }
                }
            }
        }

        // Epilogue. Stats via coalesced LDG (lane-contiguous in ch).
        // row2 duplication (r=35,36): d>=3 clamped -> result equals d-2.
        const int giA = ((b * 37 + r) * 12 + j) * 128 + ch;
        const float na = g_nA[giA];
        const float ra = g_rA[giA];
        const u64 na2 = pk2(na, na);
        const u64 ra2 = pk2(ra, ra);
        float* srow = stage + jj * STAGE_ROW + c * 62 + 6 * th;

        #pragma unroll
        for (int d = 0; d < 5; d++) {
            bool clamp = false;
            int  rowB  = r + d;
            if (d >= 3) { clamp = (r + d > 38); if (clamp) rowB = r + d - 2; }
            const int gbase = ((b * 39 + rowB) * 6 + 3 * th) * 128 + ch;
            #pragma unroll
            for (int tt = 0; tt < 3; tt++) {
                u64 s = acc[d][tt];
                if (d >= 3) s = clamp ? acc[d - 2][tt] : s;
                u64 mbp = mBv[gbase + tt * 128];
                u64 rbp = rBv[gbase + tt * 128];
                u64 res = mul2_(fma2_(na2, mbp, s), mul2_(ra2, rbp));
                *(u64*)(srow + 12 * d + 2 * tt) = res;
            }
        }
        __syncthreads();

        // Flush: 6 j-tiles, each 32c x 60w floats = 960 u64 in gmem order.
        // Stage u64 index (c,k) = c*31 + k; gmem u64 index = c*30 + k.
        {
            u64* og0 = (u64*)(out + ((b * 37 + r) * 12 + 6 * ph) * 7680
                                  + chq * 1920);
            #pragma unroll 1
            for (int jl = 0; jl < 6; jl++) {
                const u64* st0 = (const u64*)(stage + jl * STAGE_ROW);
                u64* og = og0 + jl * 3840;
                og[c1 * 30 + k1] = st0[c1 * 31 + k1];
                og[c2 * 30 + k2] = st0[c2 * 31 + k2];
                if (tid < 192)
                    og[c3 * 30 + k3] = st0[c3 * 31 + k3];
            }
        }
        __syncthreads();
    }
}

// ---------------------------------------------------------------------------
extern "C" void kernel_launch(void* const* d_in, const int* in_sizes, int n_in,
                              void* d_out, int out_size)
{
    const float* in1 = (const float*)d_in[0];
    const float* in2 = (const float*)d_in[1];
    float* out = (float*)d_out;

    cudaFuncSetAttribute(nc_corr_kernel,
                         cudaFuncAttributeMaxDynamicSharedMemorySize, SMEM_BYTES);

    nc_stats_kernel<<<dim3(NR + 39, NB), 384>>>(in1, in2);
    nc_corr_kernel<<<dim3(NR, NB, 4), 384, SMEM_BYTES>>>(in1, in2, out);
}